// round 10
// baseline (speedup 1.0000x reference)
#include <cuda_runtime.h>

// Problem constants
#define BB      16
#define TT      1024
#define NK      1024
#define DD      256
#define WIN     64
#define TILE_T  32

// Shared-memory layout (floats). 260-float row stride => 4-bank shift per row.
#define QS_STRIDE   260
#define KS_STRIDE   260
#define PS_STRIDE   68

#define QS_OFF      0
#define KS_OFF      (TILE_T * QS_STRIDE)                 // 8320
#define PS_OFF      (KS_OFF + WIN * KS_STRIDE)           // 24960
#define SMEM_FLOATS (PS_OFF + TILE_T * PS_STRIDE)        // 27136 floats
#define SMEM_BYTES  (SMEM_FLOATS * 4)                    // 108544 B -> 2 CTAs/SM

// Output layout: R (B,T,512) | alignments (B,N,T) | max_attentions (B,T)
#define R_ELEMS   ((size_t)BB * TT * (2 * DD))           // 8,388,608
#define AL_ELEMS  ((size_t)BB * NK * TT)                 // 16,777,216

typedef unsigned long long u64;
typedef unsigned int       u32;

union UF2 { u64 u; float2 f; };

// Packed fp32x2 FMA (Blackwell FFMA2) — exact fp32, 2x FFMA throughput.
__device__ __forceinline__ u64 fma2(u64 a, u64 b, u64 c) {
    u64 d;
    asm("fma.rn.f32x2 %0, %1, %2, %3;" : "=l"(d) : "l"(a), "l"(b), "l"(c));
    return d;
}

// 16-byte async global->shared copy (LDGSTS).
__device__ __forceinline__ void cp_async16(u32 smem_addr, const void* gptr) {
    asm volatile("cp.async.cg.shared.global [%0], [%1], 16;"
                 :: "r"(smem_addr), "l"(gptr));
}
__device__ __forceinline__ void cp_async_commit() {
    asm volatile("cp.async.commit_group;");
}
__device__ __forceinline__ void cp_async_wait_all() {
    asm volatile("cp.async.wait_group 0;");
}

__global__ __launch_bounds__(256, 2)
void attn_win_kernel(const float* __restrict__ Q,
                     const float* __restrict__ K,
                     const float* __restrict__ V,
                     const int*   __restrict__ prev_words,  // raw words of prev_max_attentions
                     float* __restrict__ out)
{
    extern __shared__ float smem[];
    float* Qs = smem + QS_OFF;
    float* Ks = smem + KS_OFF;   // K window during QK, then reused for V window
    float* Ps = smem + PS_OFF;

    const int tid = threadIdx.x;
    const int b   = blockIdx.y;
    const int t0  = blockIdx.x * TILE_T;

    // dtype sniff: int64 (little-endian, values < 2^31) has zero high words.
    int odd_or = prev_words[1] | prev_words[3] | prev_words[5] | prev_words[7] |
                 prev_words[9] | prev_words[11] | prev_words[13] | prev_words[15];
    const int prev = (odd_or == 0) ? prev_words[2 * b] : prev_words[b];

    float* Rout = out;                       // (B,T,512)
    float* Aout = out + R_ELEMS;             // (B,N,T), zero-filled below
    float* Mout = Aout + AL_ELEMS;           // (B,T)

    // ---------------- K window -> smem via cp.async (starts first) -----------
    {
        const char* Kg = (const char*)(K + ((size_t)b * NK + prev) * DD);
        #pragma unroll
        for (int it = 0; it < (WIN * DD / 4) / 256; ++it) {      // 16 iters
            int idx = tid + it * 256;
            int j   = idx >> 6;          // 0..63
            int d4  = idx & 63;
            u32 dst = (u32)__cvta_generic_to_shared(Ks + j * KS_STRIDE + d4 * 4);
            cp_async16(dst, Kg + (size_t)(j * 64 + d4) * 16);
        }
        cp_async_commit();
    }
    // ---------------- Q tile -> smem, and copy into R[:, :, 256:512] ---------
    {
        const float4* Qg = (const float4*)(Q + ((size_t)b * TT + t0) * DD);
        #pragma unroll
        for (int it = 0; it < (TILE_T * DD / 4) / 256; ++it) {   // 8 iters
            int idx = tid + it * 256;
            int t   = idx >> 6;          // 0..31
            int d4  = idx & 63;          // 0..63 (float4 index)
            float4 q4 = __ldg(&Qg[t * 64 + d4]);
            *(float4*)(Qs + t * QS_STRIDE + d4 * 4) = q4;
            __stcs((float4*)(Rout + ((size_t)b * TT + t0 + t) * (2 * DD) + DD + d4 * 4), q4);
        }
    }
    cp_async_wait_all();
    __syncthreads();

    // =================== WARP-SPECIALIZED PHASE ==============================
    if (tid < 128) {
        // ------------- QK^T on warps 0-3: 8 t-rows x 4 j-cols per thread,
        // over HALF of D (dh = lane bit 3). Partner lane (dh^1) = laneid^8;
        // cross-d reduction via shfl_xor. 12 LDS.128 feed 64 FFMA2 per iter
        // (3 B/FFMA2 smem return traffic; warp-level 1536 LDS.128/CTA).
        const int jg  = tid & 7;
        const int dh  = (tid >> 3) & 1;            // d half
        const int tgl = (tid >> 4) & 1;
        const int w   = tid >> 5;                  // warp 0..3
        const int jh  = w & 1;                     // j half
        const int tg  = (w >> 1) * 2 + tgl;        // 0..3 -> rows 8*tg..+7
        const float* qb = Qs + (size_t)(tg * 8) * QS_STRIDE + dh * 128;
        const float* kb = Ks + (size_t)(jh * 32 + jg) * KS_STRIDE + dh * 128;

        u64 acc[8][4];
        #pragma unroll
        for (int i = 0; i < 8; ++i)
            #pragma unroll
            for (int c = 0; c < 4; ++c) acc[i][c] = 0ull;

        #pragma unroll 2
        for (int d4 = 0; d4 < 32; ++d4) {          // 128 floats = half of D
            ulonglong2 k0 = *(const ulonglong2*)(kb + 0 * 8 * KS_STRIDE + d4 * 4);
            ulonglong2 k1 = *(const ulonglong2*)(kb + 1 * 8 * KS_STRIDE + d4 * 4);
            ulonglong2 k2 = *(const ulonglong2*)(kb + 2 * 8 * KS_STRIDE + d4 * 4);
            ulonglong2 k3 = *(const ulonglong2*)(kb + 3 * 8 * KS_STRIDE + d4 * 4);
            #pragma unroll
            for (int i = 0; i < 8; ++i) {
                ulonglong2 q = *(const ulonglong2*)(qb + (size_t)i * QS_STRIDE + d4 * 4);
                acc[i][0] = fma2(q.x, k0.x, acc[i][0]);
                acc[i][0] = fma2(q.y, k0.y, acc[i][0]);
                acc[i][1] = fma2(q.x, k1.x, acc[i][1]);
                acc[i][1] = fma2(q.y, k1.y, acc[i][1]);
                acc[i][2] = fma2(q.x, k2.x, acc[i][2]);
                acc[i][2] = fma2(q.y, k2.y, acc[i][2]);
                acc[i][3] = fma2(q.x, k3.x, acc[i][3]);
                acc[i][3] = fma2(q.y, k3.y, acc[i][3]);
            }
        }
        // Cross-d reduction (partner = lane^8) + store own half of the rows.
        const int i0 = dh * 4;                     // this lane stores rows i0..i0+3
        #pragma unroll
        for (int i = 0; i < 8; ++i) {
            #pragma unroll
            for (int c = 0; c < 4; ++c) {
                UF2 u; u.u = acc[i][c];
                float s = u.f.x + u.f.y;
                s += __shfl_xor_sync(0xffffffffu, s, 8);
                if (i >= i0 && i < i0 + 4)
                    Ps[(tg * 8 + i) * PS_STRIDE + jh * 32 + jg + 8 * c] = s * 0.0625f;
            }
        }
    } else {
        // ------------- zero-fill non-window rows of alignments (warps 4-7) ---
        // Pure STG to global: overlaps fully with the QK compute above.
        const int t2   = tid - 128;
        const int rown = t2 >> 3;           // 0..15
        const int c4   = t2 & 7;            // float4 col of the 32 t-cols
        float* base = Aout + (size_t)b * NK * TT + t0 + 4 * c4;
        const float4 z = make_float4(0.f, 0.f, 0.f, 0.f);
        #pragma unroll 4
        for (int pass = 0; pass < NK / 16; ++pass) {
            int n = pass * 16 + rown;
            if ((unsigned)(n - prev) >= WIN)
                __stcs((float4*)(base + (size_t)n * TT), z);
        }
    }
    __syncthreads();   // Ks (K data) dead; Ps scores complete; zero-fill issued

    // ---------------- V window -> smem (reusing Ks) via cp.async -------------
    {
        const char* Vg = (const char*)(V + ((size_t)b * NK + prev) * DD);
        #pragma unroll
        for (int it = 0; it < (WIN * DD / 4) / 256; ++it) {      // 16 iters
            int idx = tid + it * 256;
            int j   = idx >> 6;          // 0..63
            int d4  = idx & 63;
            u32 dst = (u32)__cvta_generic_to_shared(Ks + j * KS_STRIDE + d4 * 4);
            cp_async16(dst, Vg + (size_t)(j * 64 + d4) * 16);
        }
        cp_async_commit();
    }

    // ---------------- softmax over 64 window cols + argmax -------------------
    {
        const int lane = tid & 31;
        const int w    = tid >> 5;                 // 8 warps x 4 rows
        #pragma unroll
        for (int rr = 0; rr < TILE_T / 8; ++rr) {
            int r = w * (TILE_T / 8) + rr;
            float v0 = Ps[r * PS_STRIDE + lane];
            float v1 = Ps[r * PS_STRIDE + lane + 32];
            float bv; int bi;
            if (v0 >= v1) { bv = v0; bi = lane; } else { bv = v1; bi = lane + 32; }
            #pragma unroll
            for (int off = 16; off > 0; off >>= 1) {
                float ov = __shfl_xor_sync(0xffffffffu, bv, off);
                int   oi = __shfl_xor_sync(0xffffffffu, bi, off);
                if (ov > bv || (ov == bv && oi < bi)) { bv = ov; bi = oi; }
            }
            float e0 = __expf(v0 - bv);
            float e1 = __expf(v1 - bv);
            float s = e0 + e1;
            #pragma unroll
            for (int off = 16; off > 0; off >>= 1)
                s += __shfl_xor_sync(0xffffffffu, s, off);
            float inv = 1.0f / s;
            Ps[r * PS_STRIDE + lane]      = e0 * inv;
            Ps[r * PS_STRIDE + lane + 32] = e1 * inv;
            if (lane == 0)
                Mout[(size_t)b * TT + t0 + r] = (float)(prev + bi);
        }
    }
    cp_async_wait_all();
    __syncthreads();   // probs + V-in-smem visible to all

    // ---------------- scatter probs into window rows of alignments -----------
    {
        const int rown = tid >> 3;          // 0..31
        const int c4   = tid & 7;
        float* base = Aout + (size_t)b * NK * TT + t0 + 4 * c4;
        #pragma unroll
        for (int pass = 0; pass < 2; ++pass) {
            int j = pass * 32 + rown;       // 0..63 window col
            int t = 4 * c4;
            float4 v;
            v.x = Ps[(t + 0) * PS_STRIDE + j];
            v.y = Ps[(t + 1) * PS_STRIDE + j];
            v.z = Ps[(t + 2) * PS_STRIDE + j];
            v.w = Ps[(t + 3) * PS_STRIDE + j];
            __stcs((float4*)(base + (size_t)(prev + j) * TT), v);
        }
    }

    // ---------------- P @ V_window -> R[:, :, 0:256] --------------------------
    // V in smem; thread owns 8 t-rows and one float4 d-column.
    {
        const int d8 = tid & 63;                   // float4 index 0..63
        const int tg = tid >> 6;                   // 0..3 -> rows 8*tg..+7
        u64 acc[8][2];
        #pragma unroll
        for (int r = 0; r < 8; ++r) { acc[r][0] = 0ull; acc[r][1] = 0ull; }

        #pragma unroll 2
        for (int j4 = 0; j4 < WIN / 4; ++j4) {
            ulonglong2 vv[4];
            #pragma unroll
            for (int jj = 0; jj < 4; ++jj)
                vv[jj] = *(const ulonglong2*)(Ks + (size_t)(j4 * 4 + jj) * KS_STRIDE + d8 * 4);
            #pragma unroll
            for (int r = 0; r < 8; ++r) {
                float4 p4 = *(const float4*)(Ps + (tg * 8 + r) * PS_STRIDE + j4 * 4);
                UF2 pp;
                pp.f = make_float2(p4.x, p4.x);
                acc[r][0] = fma2(pp.u, vv[0].x, acc[r][0]);
                acc[r][1] = fma2(pp.u, vv[0].y, acc[r][1]);
                pp.f = make_float2(p4.y, p4.y);
                acc[r][0] = fma2(pp.u, vv[1].x, acc[r][0]);
                acc[r][1] = fma2(pp.u, vv[1].y, acc[r][1]);
                pp.f = make_float2(p4.z, p4.z);
                acc[r][0] = fma2(pp.u, vv[2].x, acc[r][0]);
                acc[r][1] = fma2(pp.u, vv[2].y, acc[r][1]);
                pp.f = make_float2(p4.w, p4.w);
                acc[r][0] = fma2(pp.u, vv[3].x, acc[r][0]);
                acc[r][1] = fma2(pp.u, vv[3].y, acc[r][1]);
            }
        }
        #pragma unroll
        for (int r = 0; r < 8; ++r) {
            float* dst = Rout + ((size_t)b * TT + t0 + tg * 8 + r) * (2 * DD) + 4 * d8;
            float4 o;
            o.x = ((UF2*)&acc[r][0])->f.x;  o.y = ((UF2*)&acc[r][0])->f.y;
            o.z = ((UF2*)&acc[r][1])->f.x;  o.w = ((UF2*)&acc[r][1])->f.y;
            __stcs((float4*)dst, o);
        }
    }
}

extern "C" void kernel_launch(void* const* d_in, const int* in_sizes, int n_in,
                              void* d_out, int out_size)
{
    const float* Q  = (const float*)d_in[0];
    const float* K  = (const float*)d_in[1];
    const float* V  = (const float*)d_in[2];
    const int* prevw = (const int*)d_in[3];   // int64 or int32, sniffed in-kernel
    float* out = (float*)d_out;

    cudaFuncSetAttribute(attn_win_kernel,
                         cudaFuncAttributeMaxDynamicSharedMemorySize, SMEM_BYTES);

    dim3 grid(TT / TILE_T, BB);
    attn_win_kernel<<<grid, 256, SMEM_BYTES, 0>>>(Q, K, V, prevw, out);
}